// round 1
// baseline (speedup 1.0000x reference)
#include <cuda_runtime.h>
#include <math.h>

// Problem constants
#define Bq   1024
#define Ndim 128
#define Mcb  8192
#define Spay 256
#define EPST 1e-3f
#define PI_F 3.14159265358979323846f
#define TINY 1.17549435e-38f

// Gauss-Hermite K=8 nodes/weights (numpy.polynomial.hermite.hermgauss(8))
__constant__ float GHT[8] = {
    -2.9306374202572440f, -1.9816567566958429f, -1.1571937124467802f, -0.3811869902073221f,
     0.3811869902073221f,  1.1571937124467802f,  1.9816567566958429f,  2.9306374202572440f};
__constant__ float GHW[8] = {
    1.9960407221136762e-04f, 1.7077983007413475e-02f, 2.0780232581489188e-01f, 6.6114701255824130e-01f,
    6.6114701255824130e-01f, 2.0780232581489188e-01f, 1.7077983007413475e-02f, 1.9960407221136762e-04f};

// Scratch (device globals; no allocation allowed)
__device__ float g_dur[Bq * Ndim];
__device__ float g_dui[Bq * Ndim];
__device__ float g_z2[Bq];
__device__ float g_djr[Mcb * Ndim];
__device__ float g_dji[Mcb * Ndim];
__device__ float g_cr[Mcb];
__device__ float g_ci[Mcb];
__device__ float g_zj2[Mcb];
__device__ float g_isp[Mcb];    // pi / sigma_par
__device__ float g_isq[Mcb];    // pi / sigma_perp
__device__ float g_wfac[Mcb];   // alpha * sqrt(sp) / pi
__device__ float g_scale[Mcb];  // sqrt(sp / pi)
__device__ float g_W[(size_t)Bq * Mcb];
__device__ float g_den[Bq];

// ---------------------------------------------------------------------------
// K0: per-query preprocessing. grid = B, block = 128 (= N)
// ---------------------------------------------------------------------------
__global__ void prep_q(const float* __restrict__ zr, const float* __restrict__ zi,
                       const float* __restrict__ dr, const float* __restrict__ di) {
    int b = blockIdx.x;
    int t = threadIdx.x;
    __shared__ float s1[128], s2[128];
    float drv = dr[b * Ndim + t], dvv = di[b * Ndim + t];
    float zrv = zr[b * Ndim + t], zvv = zi[b * Ndim + t];
    s1[t] = drv * drv + dvv * dvv;
    s2[t] = zrv * zrv + zvv * zvv;
    __syncthreads();
    for (int o = 64; o > 0; o >>= 1) {
        if (t < o) { s1[t] += s1[t + o]; s2[t] += s2[t + o]; }
        __syncthreads();
    }
    float n = sqrtf(s1[0]);
    if (n == 0.0f) n = 1.0f;
    float inv = 1.0f / n;
    g_dur[b * Ndim + t] = drv * inv;
    g_dui[b * Ndim + t] = dvv * inv;
    if (t == 0) g_z2[b] = s2[0];
}

// ---------------------------------------------------------------------------
// K1: per-code preprocessing. grid = M, block = 128 (= N)
// ---------------------------------------------------------------------------
__global__ void prep_c(const float* __restrict__ zjr, const float* __restrict__ zji,
                       const float* __restrict__ djr_in, const float* __restrict__ dji_in,
                       const float* __restrict__ alpha, const float* __restrict__ spv,
                       const float* __restrict__ sqv) {
    int m = blockIdx.x;
    int t = threadIdx.x;
    __shared__ float s1[128], s2[128], s3[128];
    float ar = djr_in[m * Ndim + t], ai = dji_in[m * Ndim + t];
    s1[t] = ar * ar + ai * ai;
    __syncthreads();
    for (int o = 64; o > 0; o >>= 1) {
        if (t < o) s1[t] += s1[t + o];
        __syncthreads();
    }
    float n = sqrtf(s1[0]);
    if (n == 0.0f) n = 1.0f;
    float inv = 1.0f / n;
    ar *= inv; ai *= inv;
    g_djr[m * Ndim + t] = ar;
    g_dji[m * Ndim + t] = ai;
    float br = zjr[m * Ndim + t], bi = zji[m * Ndim + t];
    __syncthreads();
    s1[t] = ar * br + ai * bi;   // cr
    s2[t] = ar * bi - ai * br;   // ci
    s3[t] = br * br + bi * bi;   // |zj|^2
    __syncthreads();
    for (int o = 64; o > 0; o >>= 1) {
        if (t < o) { s1[t] += s1[t + o]; s2[t] += s2[t + o]; s3[t] += s3[t + o]; }
        __syncthreads();
    }
    if (t == 0) {
        float a  = fmaxf(alpha[m], TINY);
        float sp = fmaxf(spv[m], TINY);
        float sq = fmaxf(sqv[m], TINY);
        g_cr[m] = s1[0];
        g_ci[m] = s2[0];
        g_zj2[m] = s3[0];
        g_isp[m] = PI_F / sp;
        g_isq[m] = PI_F / sq;
        g_scale[m] = sqrtf(sp / PI_F);
        g_wfac[m] = a * sqrtf(sp) / PI_F;
    }
}

// ---------------------------------------------------------------------------
// K2: W[b,m] = alpha*align*rho. Fused 5-output GEMM + quad epilogue.
// Tile 64(b) x 64(m), 256 threads, 4x4 microtile, K-chunk 16.
// ---------------------------------------------------------------------------
#define BB 64
#define BM 64
#define KC 16

__global__ __launch_bounds__(256, 1) void wkern(
    const float* __restrict__ zr, const float* __restrict__ zi,
    const float* __restrict__ zjr, const float* __restrict__ zji) {
    __shared__ float sQ[4][KC][BB];  // zr, zi, ur, ui (transposed: [k][b])
    __shared__ float sC[4][KC][BM];  // ar, ai, br, bi (transposed: [k][m])

    const int m0 = blockIdx.x * BM;
    const int b0 = blockIdx.y * BB;
    const int t = threadIdx.x;
    const int tx = t & 15, ty = t >> 4;
    const int lrow = t & 63, lk4 = t >> 6;  // loader: row 0..63, k-quad 0..3

    float a1[4][4] = {}, a2[4][4] = {}, a3[4][4] = {}, a4[4][4] = {}, a5[4][4] = {};

    for (int k0 = 0; k0 < Ndim; k0 += KC) {
        // --- load tiles (float4 global, transpose into smem) ---
        {
            const int gq = (b0 + lrow) * Ndim + k0 + lk4 * 4;
            const int gc = (m0 + lrow) * Ndim + k0 + lk4 * 4;
            float4 v;
            v = *(const float4*)&zr[gq];
            sQ[0][lk4 * 4 + 0][lrow] = v.x; sQ[0][lk4 * 4 + 1][lrow] = v.y;
            sQ[0][lk4 * 4 + 2][lrow] = v.z; sQ[0][lk4 * 4 + 3][lrow] = v.w;
            v = *(const float4*)&zi[gq];
            sQ[1][lk4 * 4 + 0][lrow] = v.x; sQ[1][lk4 * 4 + 1][lrow] = v.y;
            sQ[1][lk4 * 4 + 2][lrow] = v.z; sQ[1][lk4 * 4 + 3][lrow] = v.w;
            v = *(const float4*)&g_dur[gq];
            sQ[2][lk4 * 4 + 0][lrow] = v.x; sQ[2][lk4 * 4 + 1][lrow] = v.y;
            sQ[2][lk4 * 4 + 2][lrow] = v.z; sQ[2][lk4 * 4 + 3][lrow] = v.w;
            v = *(const float4*)&g_dui[gq];
            sQ[3][lk4 * 4 + 0][lrow] = v.x; sQ[3][lk4 * 4 + 1][lrow] = v.y;
            sQ[3][lk4 * 4 + 2][lrow] = v.z; sQ[3][lk4 * 4 + 3][lrow] = v.w;
            v = *(const float4*)&g_djr[gc];
            sC[0][lk4 * 4 + 0][lrow] = v.x; sC[0][lk4 * 4 + 1][lrow] = v.y;
            sC[0][lk4 * 4 + 2][lrow] = v.z; sC[0][lk4 * 4 + 3][lrow] = v.w;
            v = *(const float4*)&g_dji[gc];
            sC[1][lk4 * 4 + 0][lrow] = v.x; sC[1][lk4 * 4 + 1][lrow] = v.y;
            sC[1][lk4 * 4 + 2][lrow] = v.z; sC[1][lk4 * 4 + 3][lrow] = v.w;
            v = *(const float4*)&zjr[gc];
            sC[2][lk4 * 4 + 0][lrow] = v.x; sC[2][lk4 * 4 + 1][lrow] = v.y;
            sC[2][lk4 * 4 + 2][lrow] = v.z; sC[2][lk4 * 4 + 3][lrow] = v.w;
            v = *(const float4*)&zji[gc];
            sC[3][lk4 * 4 + 0][lrow] = v.x; sC[3][lk4 * 4 + 1][lrow] = v.y;
            sC[3][lk4 * 4 + 2][lrow] = v.z; sC[3][lk4 * 4 + 3][lrow] = v.w;
        }
        __syncthreads();

#pragma unroll
        for (int kk = 0; kk < KC; kk++) {
            float4 v;
            float qzr[4], qzi[4], qur[4], qui[4], car[4], cai[4], cbr[4], cbi[4];
            v = *(const float4*)&sQ[0][kk][ty * 4]; qzr[0] = v.x; qzr[1] = v.y; qzr[2] = v.z; qzr[3] = v.w;
            v = *(const float4*)&sQ[1][kk][ty * 4]; qzi[0] = v.x; qzi[1] = v.y; qzi[2] = v.z; qzi[3] = v.w;
            v = *(const float4*)&sQ[2][kk][ty * 4]; qur[0] = v.x; qur[1] = v.y; qur[2] = v.z; qur[3] = v.w;
            v = *(const float4*)&sQ[3][kk][ty * 4]; qui[0] = v.x; qui[1] = v.y; qui[2] = v.z; qui[3] = v.w;
            v = *(const float4*)&sC[0][kk][tx * 4]; car[0] = v.x; car[1] = v.y; car[2] = v.z; car[3] = v.w;
            v = *(const float4*)&sC[1][kk][tx * 4]; cai[0] = v.x; cai[1] = v.y; cai[2] = v.z; cai[3] = v.w;
            v = *(const float4*)&sC[2][kk][tx * 4]; cbr[0] = v.x; cbr[1] = v.y; cbr[2] = v.z; cbr[3] = v.w;
            v = *(const float4*)&sC[3][kk][tx * 4]; cbi[0] = v.x; cbi[1] = v.y; cbi[2] = v.z; cbi[3] = v.w;
#pragma unroll
            for (int i = 0; i < 4; i++) {
#pragma unroll
                for (int j = 0; j < 4; j++) {
                    a1[i][j] += qzr[i] * car[j] + qzi[i] * cai[j];
                    a2[i][j] += qzi[i] * car[j] - qzr[i] * cai[j];
                    a3[i][j] += qzr[i] * cbr[j] + qzi[i] * cbi[j];
                    a4[i][j] += qur[i] * car[j] + qui[i] * cai[j];
                    a5[i][j] += qui[i] * car[j] - qur[i] * cai[j];
                }
            }
        }
        __syncthreads();
    }

    // --- epilogue: quadrature + weights ---
    const int mb = m0 + tx * 4;
    float4 f;
    float crA[4], ciA[4], zj2A[4], ispA[4], isqA[4], wfA[4], scA[4];
    f = *(const float4*)&g_cr[mb];    crA[0] = f.x; crA[1] = f.y; crA[2] = f.z; crA[3] = f.w;
    f = *(const float4*)&g_ci[mb];    ciA[0] = f.x; ciA[1] = f.y; ciA[2] = f.z; ciA[3] = f.w;
    f = *(const float4*)&g_zj2[mb];   zj2A[0] = f.x; zj2A[1] = f.y; zj2A[2] = f.z; zj2A[3] = f.w;
    f = *(const float4*)&g_isp[mb];   ispA[0] = f.x; ispA[1] = f.y; ispA[2] = f.z; ispA[3] = f.w;
    f = *(const float4*)&g_isq[mb];   isqA[0] = f.x; isqA[1] = f.y; isqA[2] = f.z; isqA[3] = f.w;
    f = *(const float4*)&g_wfac[mb];  wfA[0] = f.x; wfA[1] = f.y; wfA[2] = f.z; wfA[3] = f.w;
    f = *(const float4*)&g_scale[mb]; scA[0] = f.x; scA[1] = f.y; scA[2] = f.z; scA[3] = f.w;

#pragma unroll
    for (int i = 0; i < 4; i++) {
        const int b = b0 + ty * 4 + i;
        const float z2v = g_z2[b];
        float w4[4];
#pragma unroll
        for (int j = 0; j < 4; j++) {
            float pr = a1[i][j] - crA[j];
            float pim = a2[i][j] - ciA[j];
            float dz2 = z2v + zj2A[j] - 2.0f * a3[i][j];
            float pp = pr * pr + pim * pim;
            float perp2 = fmaxf(dz2 - pp, 0.0f);
            float align = a4[i][j] * a4[i][j] + a5[i][j] * a5[i][j];
            float base = -ispA[j] * (pim * pim) - isqA[j] * perp2;
            float ssum = 0.0f;
#pragma unroll
            for (int k = 0; k < 8; k++) {
                float d = pr - GHT[k] * scA[j];
                ssum += GHW[k] * __expf(fmaf(-ispA[j] * d, d, base));
            }
            w4[j] = wfA[j] * align * ssum;
        }
        *(float4*)&g_W[(size_t)b * Mcb + mb] = make_float4(w4[0], w4[1], w4[2], w4[3]);
    }
}

// ---------------------------------------------------------------------------
// K3: den[b] = sum_m W[b,m] + EPS. grid = B, block = 256
// ---------------------------------------------------------------------------
__global__ void denk() {
    int b = blockIdx.x;
    int t = threadIdx.x;
    float s = 0.0f;
    const float* row = &g_W[(size_t)b * Mcb];
    for (int m = t; m < Mcb; m += 256) s += row[m];
    __shared__ float sh[256];
    sh[t] = s;
    __syncthreads();
    for (int o = 128; o > 0; o >>= 1) {
        if (t < o) sh[t] += sh[t + o];
        __syncthreads();
    }
    if (t == 0) g_den[b] = sh[0] + EPST;
}

// ---------------------------------------------------------------------------
// K4: out = (W @ [T_re | T_im]) / den, written as [B, S, 2].
// Tile 64(b) x 64(s-cat), 256 threads, 4x4 microtile, K-chunk 16 over M.
// ---------------------------------------------------------------------------
__global__ __launch_bounds__(256, 2) void outk(const float* __restrict__ Tre,
                                               const float* __restrict__ Tim,
                                               float* __restrict__ out) {
    __shared__ float sW[KC][64];
    __shared__ float sT[KC][64];
    const int s0 = blockIdx.x * 64;      // 0..511 concatenated [re|im]
    const int b0 = blockIdx.y * 64;
    const float* Tsel = (s0 < Spay) ? Tre : Tim;
    const int col0 = s0 & (Spay - 1);
    const int t = threadIdx.x;
    const int tx = t & 15, ty = t >> 4;
    const int lb = t & 63, lm4 = t >> 6;   // W loader
    const int lc4 = t & 15, lr = t >> 4;   // T loader

    float acc[4][4] = {};

    for (int k0 = 0; k0 < Mcb; k0 += KC) {
        float4 wv = *(const float4*)&g_W[(size_t)(b0 + lb) * Mcb + k0 + lm4 * 4];
        sW[lm4 * 4 + 0][lb] = wv.x; sW[lm4 * 4 + 1][lb] = wv.y;
        sW[lm4 * 4 + 2][lb] = wv.z; sW[lm4 * 4 + 3][lb] = wv.w;
        *(float4*)&sT[lr][lc4 * 4] = *(const float4*)&Tsel[(k0 + lr) * Spay + col0 + lc4 * 4];
        __syncthreads();
#pragma unroll
        for (int kk = 0; kk < KC; kk++) {
            float4 w4 = *(const float4*)&sW[kk][ty * 4];
            float4 t4 = *(const float4*)&sT[kk][tx * 4];
            float wa[4] = {w4.x, w4.y, w4.z, w4.w};
            float ta[4] = {t4.x, t4.y, t4.z, t4.w};
#pragma unroll
            for (int i = 0; i < 4; i++)
#pragma unroll
                for (int j = 0; j < 4; j++) acc[i][j] += wa[i] * ta[j];
        }
        __syncthreads();
    }

#pragma unroll
    for (int i = 0; i < 4; i++) {
        const int b = b0 + ty * 4 + i;
        const float inv = 1.0f / g_den[b];
#pragma unroll
        for (int j = 0; j < 4; j++) {
            const int sg = s0 + tx * 4 + j;
            const int c = sg >> 8;           // 0 = re, 1 = im
            const int sl = sg & (Spay - 1);
            out[((size_t)b * Spay + sl) * 2 + c] = acc[i][j] * inv;
        }
    }
}

// ---------------------------------------------------------------------------
extern "C" void kernel_launch(void* const* d_in, const int* in_sizes, int n_in,
                              void* d_out, int out_size) {
    const float* z_re  = (const float*)d_in[0];
    const float* z_im  = (const float*)d_in[1];
    const float* d_re  = (const float*)d_in[2];
    const float* d_im  = (const float*)d_in[3];
    const float* zj_re = (const float*)d_in[4];
    const float* zj_im = (const float*)d_in[5];
    const float* dj_re = (const float*)d_in[6];
    const float* dj_im = (const float*)d_in[7];
    const float* T_re  = (const float*)d_in[8];
    const float* T_im  = (const float*)d_in[9];
    const float* alpha = (const float*)d_in[10];
    const float* s_par = (const float*)d_in[11];
    const float* s_perp = (const float*)d_in[12];
    float* out = (float*)d_out;

    prep_q<<<Bq, 128>>>(z_re, z_im, d_re, d_im);
    prep_c<<<Mcb, 128>>>(zj_re, zj_im, dj_re, dj_im, alpha, s_par, s_perp);
    wkern<<<dim3(Mcb / BM, Bq / BB), 256>>>(z_re, z_im, zj_re, zj_im);
    denk<<<Bq, 256>>>();
    outk<<<dim3(2 * Spay / 64, Bq / 64), 256>>>(T_re, T_im, out);
}

// round 4
// speedup vs baseline: 3.1542x; 3.1542x over previous
#include <cuda_runtime.h>
#include <cuda_bf16.h>
#include <math.h>
#include <stdint.h>

#define Bq   1024
#define Ndim 128
#define Mcb  8192
#define Spay 256
#define EPST 1e-3f
#define PI_F 3.14159265358979323846f
#define TINY 1.17549435e-38f

__constant__ float GHT[8] = {
    -2.9306374202572440f, -1.9816567566958429f, -1.1571937124467802f, -0.3811869902073221f,
     0.3811869902073221f,  1.1571937124467802f,  1.9816567566958429f,  2.9306374202572440f};
__constant__ float GHW[8] = {
    1.9960407221136762e-04f, 1.7077983007413475e-02f, 2.0780232581489188e-01f, 6.6114701255824130e-01f,
    6.6114701255824130e-01f, 2.0780232581489188e-01f, 1.7077983007413475e-02f, 1.9960407221136762e-04f};

// ---------------- scratch (row-major simple layouts only) ----------------
__device__ __align__(16) __nv_bfloat16 g_Ah[2][Bq * 256];   // A var 0=[zr|zi], 1=[ur|ui]
__device__ __align__(16) __nv_bfloat16 g_Al[2][Bq * 256];
__device__ __align__(16) __nv_bfloat16 g_Bh[3][Mcb * 256];  // B var 0=[ar|ai], 1=[-ai|ar], 2=[br|bi]
__device__ __align__(16) __nv_bfloat16 g_Bl[3][Mcb * 256];
__device__ __align__(16) __nv_bfloat16 g_Tth[512 * Mcb];    // Tcat^T [scat][m]
__device__ __align__(16) __nv_bfloat16 g_Ttl[512 * Mcb];
__device__ __align__(16) __nv_bfloat16 g_Whi[(size_t)Bq * Mcb];  // W [b][m]
__device__ __align__(16) __nv_bfloat16 g_Wlo[(size_t)Bq * Mcb];
__device__ __align__(16) float g_cr[Mcb], g_ci[Mcb], g_zj2[Mcb];
__device__ __align__(16) float g_isp[Mcb], g_isq[Mcb], g_wfac[Mcb], g_scale[Mcb];
__device__ float g_z2[Bq];
__device__ float g_den[Bq];
__device__ float g_dpart[Bq * 256];

// ---------------- helpers ----------------
__device__ __forceinline__ uint32_t smem_u32(const void* p) {
    uint32_t a;
    asm("{ .reg .u64 t; cvta.to.shared.u64 t, %1; cvt.u32.u64 %0, t; }" : "=r"(a) : "l"(p));
    return a;
}
__device__ __forceinline__ void cpa16(uint32_t s, const void* g) {
    asm volatile("{ .reg .u64 gg; cvta.to.global.u64 gg, %1; cp.async.cg.shared.global [%0], [gg], 16; }"
                 :: "r"(s), "l"(g) : "memory");
}
__device__ __forceinline__ void cpa_commit() { asm volatile("cp.async.commit_group;" ::: "memory"); }
__device__ __forceinline__ void cpa_wait0() { asm volatile("cp.async.wait_group 0;" ::: "memory"); }
__device__ __forceinline__ void cpa_wait1() { asm volatile("cp.async.wait_group 1;" ::: "memory"); }

__device__ __forceinline__ void mma_bf16(float* d, const uint32_t* a, const uint32_t* b) {
    asm volatile("mma.sync.aligned.m16n8k16.row.col.f32.bf16.bf16.f32 "
                 "{%0,%1,%2,%3}, {%4,%5,%6,%7}, {%8,%9}, {%0,%1,%2,%3};"
                 : "+f"(d[0]), "+f"(d[1]), "+f"(d[2]), "+f"(d[3])
                 : "r"(a[0]), "r"(a[1]), "r"(a[2]), "r"(a[3]), "r"(b[0]), "r"(b[1]));
}
__device__ __forceinline__ void ldmx4(uint32_t* r, uint32_t a) {
    asm volatile("ldmatrix.sync.aligned.m8n8.x4.shared.b16 {%0,%1,%2,%3}, [%4];"
                 : "=r"(r[0]), "=r"(r[1]), "=r"(r[2]), "=r"(r[3]) : "r"(a));
}
__device__ __forceinline__ uint32_t swz(uint32_t o) { return o ^ ((o >> 3) & 0x70); }

__device__ __forceinline__ void wsplit(__nv_bfloat16* ph, __nv_bfloat16* pl, float x) {
    __nv_bfloat16 h = __float2bfloat16(x);
    *ph = h;
    *pl = __float2bfloat16(x - __bfloat162float(h));
}
__device__ __forceinline__ void split2w(float x, float y, uint32_t& hw, uint32_t& lw) {
    __nv_bfloat16 hx = __float2bfloat16(x), hy = __float2bfloat16(y);
    __nv_bfloat16 lx = __float2bfloat16(x - __bfloat162float(hx));
    __nv_bfloat16 ly = __float2bfloat16(y - __bfloat162float(hy));
    hw = ((uint32_t)__bfloat16_as_ushort(hy) << 16) | __bfloat16_as_ushort(hx);
    lw = ((uint32_t)__bfloat16_as_ushort(ly) << 16) | __bfloat16_as_ushort(lx);
}

// ---------------------------------------------------------------------------
// prep kernels
// ---------------------------------------------------------------------------
__global__ void prep_q(const float* __restrict__ zr, const float* __restrict__ zi,
                       const float* __restrict__ dr, const float* __restrict__ di) {
    int b = blockIdx.x, t = threadIdx.x;
    __shared__ float s1[128], s2[128];
    float drv = dr[b*Ndim+t], dvv = di[b*Ndim+t];
    float zrv = zr[b*Ndim+t], ziv = zi[b*Ndim+t];
    s1[t] = drv*drv + dvv*dvv;
    s2[t] = zrv*zrv + ziv*ziv;
    __syncthreads();
    for (int o = 64; o > 0; o >>= 1) { if (t < o) { s1[t]+=s1[t+o]; s2[t]+=s2[t+o]; } __syncthreads(); }
    float n = sqrtf(s1[0]); if (n == 0.0f) n = 1.0f;
    float inv = 1.0f / n;
    float ur = drv*inv, ui = dvv*inv;
    wsplit(&g_Ah[0][b*256+t],     &g_Al[0][b*256+t],     zrv);
    wsplit(&g_Ah[0][b*256+128+t], &g_Al[0][b*256+128+t], ziv);
    wsplit(&g_Ah[1][b*256+t],     &g_Al[1][b*256+t],     ur);
    wsplit(&g_Ah[1][b*256+128+t], &g_Al[1][b*256+128+t], ui);
    if (t == 0) g_z2[b] = s2[0];
}

__global__ void prep_c(const float* __restrict__ zjr, const float* __restrict__ zji,
                       const float* __restrict__ djr, const float* __restrict__ dji,
                       const float* __restrict__ alpha, const float* __restrict__ spv,
                       const float* __restrict__ sqv) {
    int m = blockIdx.x, t = threadIdx.x;
    __shared__ float s1[128], s2[128], s3[128];
    float ar = djr[m*Ndim+t], ai = dji[m*Ndim+t];
    s1[t] = ar*ar + ai*ai;
    __syncthreads();
    for (int o = 64; o > 0; o >>= 1) { if (t < o) s1[t]+=s1[t+o]; __syncthreads(); }
    float n = sqrtf(s1[0]); if (n == 0.0f) n = 1.0f;
    float inv = 1.0f / n;
    ar *= inv; ai *= inv;
    float br = zjr[m*Ndim+t], bi = zji[m*Ndim+t];
    wsplit(&g_Bh[0][m*256+t],     &g_Bl[0][m*256+t],     ar);
    wsplit(&g_Bh[0][m*256+128+t], &g_Bl[0][m*256+128+t], ai);
    wsplit(&g_Bh[1][m*256+t],     &g_Bl[1][m*256+t],     -ai);
    wsplit(&g_Bh[1][m*256+128+t], &g_Bl[1][m*256+128+t], ar);
    wsplit(&g_Bh[2][m*256+t],     &g_Bl[2][m*256+t],     br);
    wsplit(&g_Bh[2][m*256+128+t], &g_Bl[2][m*256+128+t], bi);
    __syncthreads();
    s1[t] = ar*br + ai*bi;
    s2[t] = ar*bi - ai*br;
    s3[t] = br*br + bi*bi;
    __syncthreads();
    for (int o = 64; o > 0; o >>= 1) {
        if (t < o) { s1[t]+=s1[t+o]; s2[t]+=s2[t+o]; s3[t]+=s3[t+o]; }
        __syncthreads();
    }
    if (t == 0) {
        float a  = fmaxf(alpha[m], TINY);
        float sp = fmaxf(spv[m], TINY);
        float sq = fmaxf(sqv[m], TINY);
        g_cr[m] = s1[0]; g_ci[m] = s2[0]; g_zj2[m] = s3[0];
        g_isp[m] = PI_F / sp;
        g_isq[m] = PI_F / sq;
        g_scale[m] = sqrtf(sp / PI_F);
        g_wfac[m] = a * sqrtf(sp) / PI_F;
    }
}

// Tcat^T[scat][m], hi/lo split.  grid (16, 256), block (32, 8)
__global__ void prep_T(const float* __restrict__ Tre, const float* __restrict__ Tim) {
    __shared__ float tile[32][33];
    int sx = blockIdx.x * 32, my = blockIdx.y * 32;
    int tx = threadIdx.x, ty = threadIdx.y;
    const float* Ts = (sx < Spay) ? Tre : Tim;
    int sl = sx & (Spay - 1);
#pragma unroll
    for (int i = 0; i < 4; i++) {
        int ml = ty + i * 8;
        tile[tx][ml] = Ts[(my + ml) * Spay + sl + tx];
    }
    __syncthreads();
#pragma unroll
    for (int i = 0; i < 4; i++) {
        int srow = sx + ty + i * 8;
        float v = tile[ty + i * 8][tx];
        wsplit(&g_Tth[(size_t)srow * Mcb + my + tx], &g_Ttl[(size_t)srow * Mcb + my + tx], v);
    }
}

// ---------------------------------------------------------------------------
// wkern: split-bf16 mma.sync 5-acc GEMM (128b x 64m) + quadrature epilogue
// smem/stage: A 2 var x 128 rows x 128B (swizzled) + B 3 var x 64 rows x 128B
// ---------------------------------------------------------------------------
#define WA_REG 32768
#define WB_REG 24576
#define WSTG   (WA_REG + WB_REG)   // 57344
#define WSMEM  (2 * WSTG)          // 114688

__global__ __launch_bounds__(256, 1) void wkern() {
    extern __shared__ __align__(16) uint8_t sm[];
    const uint32_t smb = smem_u32(sm);
    const int t = threadIdx.x, wid = t >> 5, lane = t & 31;
    const int mCTA = blockIdx.x, bCTA = blockIdx.y;
    const int wb = wid >> 1, wm = wid & 1;

    float acc[5][2][4][4] = {};

    auto issue = [&](int ch) {
        int s = ch & 1;
        int grp = ch >> 2;                 // 0: hh, 1: lo(A)*hi(B), 2: hi(A)*lo(B)
        int k0 = (ch & 3) * 64;
        uint32_t dstA = smb + s * WSTG;
        uint32_t dstB = dstA + WA_REG;
        const __nv_bfloat16* A0 = (grp == 1) ? g_Al[0] : g_Ah[0];
        const __nv_bfloat16* A1 = (grp == 1) ? g_Al[1] : g_Ah[1];
        const __nv_bfloat16* B0 = (grp == 2) ? g_Bl[0] : g_Bh[0];
        const __nv_bfloat16* B1 = (grp == 2) ? g_Bl[1] : g_Bh[1];
        const __nv_bfloat16* B2 = (grp == 2) ? g_Bl[2] : g_Bh[2];
        const __nv_bfloat16* As[2] = {A0, A1};
        const __nv_bfloat16* Bs[3] = {B0, B1, B2};
#pragma unroll
        for (int i = 0; i < 8; i++) {      // A: 2048 granules of 16B
            int g = i * 256 + t;
            int var = g >> 10, row = (g >> 3) & 127, c16 = g & 7;
            const void* src = As[var] + (size_t)(bCTA*128 + row)*256 + k0 + c16*8;
            cpa16(dstA + var*16384 + swz(row*128 + c16*16), src);
        }
#pragma unroll
        for (int i = 0; i < 6; i++) {      // B: 1536 granules
            int g = i * 256 + t;
            int var = g >> 9, row = (g >> 3) & 63, c16 = g & 7;
            const void* src = Bs[var] + (size_t)(mCTA*64 + row)*256 + k0 + c16*8;
            cpa16(dstB + var*8192 + swz(row*128 + c16*16), src);
        }
        cpa_commit();
    };

    // ldmatrix per-lane row components
    const int arow = wb*32 + ((lane >> 3) & 1)*8 + (lane & 7);   // + bt*16
    const int ac16 = lane >> 4;                                   // + kt*2
    const int brow_in = ((lane >> 4) ? 8 : 0) + (lane & 7);       // nt parity*8 + row
    const int bk16 = (lane >> 3) & 1;                             // + kt*2

    auto compute = [&](int s) {
        uint32_t baseA = smb + s * WSTG;
        uint32_t baseB = baseA + WA_REG;
#pragma unroll
        for (int kt = 0; kt < 4; kt++) {
            uint32_t af[2][2][4];
#pragma unroll
            for (int var = 0; var < 2; var++)
#pragma unroll
                for (int bt = 0; bt < 2; bt++) {
                    uint32_t o = (uint32_t)(arow + bt*16)*128 + (kt*2 + ac16)*16;
                    ldmx4(af[var][bt], baseA + var*16384 + swz(o));
                }
#pragma unroll
            for (int VAR = 0; VAR < 3; VAR++) {
#pragma unroll
                for (int np = 0; np < 2; np++) {
                    // x4 covers ntiles (wm*4 + np*2) and (+1): r0,r1 = even nt, r2,r3 = odd nt
                    uint32_t bf[4];
                    uint32_t o = (uint32_t)((wm*4 + np*2)*8 + brow_in)*128 + (kt*2 + bk16)*16;
                    ldmx4(bf, baseB + VAR*8192 + swz(o));
#pragma unroll
                    for (int h = 0; h < 2; h++) {
                        int nt = np*2 + h;
                        const uint32_t* bsel = &bf[h*2];
                        if (VAR == 0) {
                            mma_bf16(acc[0][0][nt], af[0][0], bsel); mma_bf16(acc[0][1][nt], af[0][1], bsel);
                            mma_bf16(acc[3][0][nt], af[1][0], bsel); mma_bf16(acc[3][1][nt], af[1][1], bsel);
                        } else if (VAR == 1) {
                            mma_bf16(acc[1][0][nt], af[0][0], bsel); mma_bf16(acc[1][1][nt], af[0][1], bsel);
                            mma_bf16(acc[4][0][nt], af[1][0], bsel); mma_bf16(acc[4][1][nt], af[1][1], bsel);
                        } else {
                            mma_bf16(acc[2][0][nt], af[0][0], bsel); mma_bf16(acc[2][1][nt], af[0][1], bsel);
                        }
                    }
                }
            }
        }
    };

    issue(0);
    for (int ch = 0; ch < 12; ch++) {
        if (ch < 11) { issue(ch + 1); cpa_wait1(); } else { cpa_wait0(); }
        __syncthreads();
        compute(ch & 1);
        __syncthreads();
    }

    // ---- epilogue (D frag: row = lane/4 + (c>>1)*8, col = 2*(lane%4) + (c&1)) ----
    const int mBase = mCTA*64 + wm*32 + ((lane & 3) << 1);
    float2 crv[4], civ[4], zjv[4], ipv[4], iqv[4], wfv[4], scv[4];
#pragma unroll
    for (int nt = 0; nt < 4; nt++) {
        int m = mBase + nt*8;
        crv[nt] = *(const float2*)&g_cr[m];   civ[nt] = *(const float2*)&g_ci[m];
        zjv[nt] = *(const float2*)&g_zj2[m];  ipv[nt] = *(const float2*)&g_isp[m];
        iqv[nt] = *(const float2*)&g_isq[m];  wfv[nt] = *(const float2*)&g_wfac[m];
        scv[nt] = *(const float2*)&g_scale[m];
    }
    const int rBase = bCTA*128 + wb*32 + (lane >> 2);

#pragma unroll
    for (int bt = 0; bt < 2; bt++) {
        float rs[2] = {0.0f, 0.0f};
        float wv[4][4];
        float z2v[2] = { g_z2[rBase + bt*16], g_z2[rBase + bt*16 + 8] };
#pragma unroll
        for (int nt = 0; nt < 4; nt++) {
#pragma unroll
            for (int c = 0; c < 4; c++) {
                int h = c >> 1, j = c & 1;
                float cr = j ? crv[nt].y : crv[nt].x;
                float ci = j ? civ[nt].y : civ[nt].x;
                float zj = j ? zjv[nt].y : zjv[nt].x;
                float ip = j ? ipv[nt].y : ipv[nt].x;
                float iq = j ? iqv[nt].y : iqv[nt].x;
                float wf = j ? wfv[nt].y : wfv[nt].x;
                float sc = j ? scv[nt].y : scv[nt].x;
                float a1 = acc[0][bt][nt][c], a2 = acc[1][bt][nt][c];
                float a3 = acc[2][bt][nt][c], a4 = acc[3][bt][nt][c], a5 = acc[4][bt][nt][c];
                float pr = a1 - cr;
                float pim = a2 - ci;
                float dz2 = z2v[h] + zj - 2.0f * a3;
                float perp2 = fmaxf(dz2 - (pr*pr + pim*pim), 0.0f);
                float align_ = a4*a4 + a5*a5;
                float base = -ip * (pim*pim) - iq * perp2;
                float ssum = 0.0f;
#pragma unroll
                for (int k = 0; k < 8; k++) {
                    float d = pr - GHT[k] * sc;
                    ssum += GHW[k] * __expf(fmaf(-ip * d, d, base));
                }
                float w = wf * align_ * ssum;
                wv[nt][c] = w;
                rs[h] += w;
            }
        }
#pragma unroll
        for (int h = 0; h < 2; h++) {
            float v = rs[h];
            v += __shfl_xor_sync(0xffffffffu, v, 1);
            v += __shfl_xor_sync(0xffffffffu, v, 2);
            if ((lane & 3) == 0)
                g_dpart[(rBase + bt*16 + h*8) * 256 + mCTA*2 + wm] = v;
        }
        // plain row-major W store (pairs of adjacent m)
#pragma unroll
        for (int h = 0; h < 2; h++) {
            size_t rowoff = (size_t)(rBase + bt*16 + h*8) * Mcb;
#pragma unroll
            for (int nt = 0; nt < 4; nt++) {
                uint32_t hw, lw;
                split2w(wv[nt][h*2], wv[nt][h*2 + 1], hw, lw);
                *(uint32_t*)&g_Whi[rowoff + mBase + nt*8] = hw;
                *(uint32_t*)&g_Wlo[rowoff + mBase + nt*8] = lw;
            }
        }
    }
}

// ---------------------------------------------------------------------------
__global__ void denk() {
    int b = blockIdx.x, t = threadIdx.x;
    __shared__ float sh[256];
    sh[t] = g_dpart[b * 256 + t];
    __syncthreads();
    for (int o = 128; o > 0; o >>= 1) { if (t < o) sh[t] += sh[t + o]; __syncthreads(); }
    if (t == 0) g_den[b] = sh[0] + EPST;
}

// ---------------------------------------------------------------------------
// outk: out = (W @ Tcat)/den.  CTA 64b x 64scat, K = 8192 x 3 splits.
// ---------------------------------------------------------------------------
#define OW_REG 8192
#define OT_REG 8192
#define OSTG   (OW_REG + OT_REG)  // 16384
#define OSMEM  (2 * OSTG)         // 32768

__global__ __launch_bounds__(256, 2) void outk(float* __restrict__ out) {
    extern __shared__ __align__(16) uint8_t sm[];
    const uint32_t smb = smem_u32(sm);
    const int t = threadIdx.x, wid = t >> 5, lane = t & 31;
    const int sCTA = blockIdx.x, bCTA = blockIdx.y;
    const int wb = wid >> 1, ws = wid & 1;
    const int b0 = bCTA * 64, s0 = sCTA * 64;

    float acc[4][4] = {};

    auto issue = [&](int ch) {
        int s = ch & 1;
        int seg = ch >> 7;                // 0: Whi*Thi, 1: Wlo*Thi, 2: Whi*Tlo
        int k0 = (ch & 127) * 64;
        const __nv_bfloat16* Wsrc = (seg == 1) ? g_Wlo : g_Whi;
        const __nv_bfloat16* Tsrc = (seg == 2) ? g_Ttl : g_Tth;
        uint32_t dstW = smb + s * OSTG;
        uint32_t dstT = dstW + OW_REG;
#pragma unroll
        for (int i = 0; i < 2; i++) {     // W: 512 granules
            int g = i * 256 + t;
            int row = g >> 3, c16 = g & 7;
            cpa16(dstW + swz(row*128 + c16*16), Wsrc + (size_t)(b0 + row)*Mcb + k0 + c16*8);
        }
#pragma unroll
        for (int i = 0; i < 2; i++) {     // T: 512 granules
            int g = i * 256 + t;
            int row = g >> 3, c16 = g & 7;
            cpa16(dstT + swz(row*128 + c16*16), Tsrc + (size_t)(s0 + row)*Mcb + k0 + c16*8);
        }
        cpa_commit();
    };

    const int arow = wb*16 + ((lane >> 3) & 1)*8 + (lane & 7);
    const int ac16 = lane >> 4;
    const int brow_in = ((lane >> 4) ? 8 : 0) + (lane & 7);
    const int bk16 = (lane >> 3) & 1;

    auto compute = [&](int s) {
        uint32_t baseW = smb + s * OSTG;
        uint32_t baseT = baseW + OW_REG;
#pragma unroll
        for (int kt = 0; kt < 4; kt++) {
            uint32_t af[4];
            {
                uint32_t o = (uint32_t)arow*128 + (kt*2 + ac16)*16;
                ldmx4(af, baseW + swz(o));
            }
#pragma unroll
            for (int np = 0; np < 2; np++) {
                uint32_t bf[4];
                uint32_t o = (uint32_t)((ws*4 + np*2)*8 + brow_in)*128 + (kt*2 + bk16)*16;
                ldmx4(bf, baseT + swz(o));
                mma_bf16(acc[np*2],     af, &bf[0]);
                mma_bf16(acc[np*2 + 1], af, &bf[2]);
            }
        }
    };

    issue(0);
    for (int ch = 0; ch < 384; ch++) {
        if (ch < 383) { issue(ch + 1); cpa_wait1(); } else { cpa_wait0(); }
        __syncthreads();
        compute(ch & 1);
        __syncthreads();
    }

    const int sBase = s0 + ws*32 + ((lane & 3) << 1);
    const int rB = b0 + wb*16 + (lane >> 2);
#pragma unroll
    for (int h = 0; h < 2; h++) {
        int b = rB + h*8;
        float inv = 1.0f / g_den[b];
#pragma unroll
        for (int nt = 0; nt < 4; nt++) {
            int scat = sBase + nt*8;
            int c = scat >> 8;
            int sl = scat & (Spay - 1);
            out[((size_t)b * Spay + sl) * 2 + c]       = acc[nt][h*2]     * inv;
            out[((size_t)b * Spay + sl + 1) * 2 + c]   = acc[nt][h*2 + 1] * inv;
        }
    }
}

// ---------------------------------------------------------------------------
extern "C" void kernel_launch(void* const* d_in, const int* in_sizes, int n_in,
                              void* d_out, int out_size) {
    const float* z_re  = (const float*)d_in[0];
    const float* z_im  = (const float*)d_in[1];
    const float* d_re  = (const float*)d_in[2];
    const float* d_im  = (const float*)d_in[3];
    const float* zj_re = (const float*)d_in[4];
    const float* zj_im = (const float*)d_in[5];
    const float* dj_re = (const float*)d_in[6];
    const float* dj_im = (const float*)d_in[7];
    const float* T_re  = (const float*)d_in[8];
    const float* T_im  = (const float*)d_in[9];
    const float* alpha = (const float*)d_in[10];
    const float* s_par = (const float*)d_in[11];
    const float* s_perp = (const float*)d_in[12];
    float* out = (float*)d_out;

    cudaFuncSetAttribute(wkern, cudaFuncAttributeMaxDynamicSharedMemorySize, WSMEM);
    cudaFuncSetAttribute(outk,  cudaFuncAttributeMaxDynamicSharedMemorySize, OSMEM);

    prep_q<<<Bq, 128>>>(z_re, z_im, d_re, d_im);
    prep_c<<<Mcb, 128>>>(zj_re, zj_im, dj_re, dj_im, alpha, s_par, s_perp);
    prep_T<<<dim3(512 / 32, Mcb / 32), dim3(32, 8)>>>(T_re, T_im);
    wkern<<<dim3(Mcb / 64, Bq / 128), 256, WSMEM>>>();
    denk<<<Bq, 256>>>();
    outk<<<dim3(512 / 64, Bq / 64), 256, OSMEM>>>(out);
}

// round 5
// speedup vs baseline: 4.0237x; 1.2757x over previous
#include <cuda_runtime.h>
#include <cuda_bf16.h>
#include <math.h>
#include <stdint.h>

#define Bq   1024
#define Ndim 128
#define Mcb  8192
#define Spay 256
#define EPST 1e-3f
#define PI_F 3.14159265358979323846f
#define TINY 1.17549435e-38f

__constant__ float GHT[8] = {
    -2.9306374202572440f, -1.9816567566958429f, -1.1571937124467802f, -0.3811869902073221f,
     0.3811869902073221f,  1.1571937124467802f,  1.9816567566958429f,  2.9306374202572440f};
__constant__ float GHW[8] = {
    1.9960407221136762e-04f, 1.7077983007413475e-02f, 2.0780232581489188e-01f, 6.6114701255824130e-01f,
    6.6114701255824130e-01f, 2.0780232581489188e-01f, 1.7077983007413475e-02f, 1.9960407221136762e-04f};

// ---------------- scratch (row-major simple layouts only) ----------------
__device__ __align__(16) __nv_bfloat16 g_Ah[2][Bq * 256];   // A var 0=[zr|zi], 1=[ur|ui]
__device__ __align__(16) __nv_bfloat16 g_Al[2][Bq * 256];
__device__ __align__(16) __nv_bfloat16 g_Bh[3][Mcb * 256];  // B var 0=[ar|ai], 1=[-ai|ar], 2=[br|bi]
__device__ __align__(16) __nv_bfloat16 g_Bl[3][Mcb * 256];
__device__ __align__(16) __nv_bfloat16 g_Tth[512 * Mcb];    // Tcat^T [scat][m]
__device__ __align__(16) __nv_bfloat16 g_Ttl[512 * Mcb];
__device__ __align__(16) __nv_bfloat16 g_Whi[(size_t)Bq * Mcb];  // W [b][m]
__device__ __align__(16) __nv_bfloat16 g_Wlo[(size_t)Bq * Mcb];
__device__ __align__(16) float g_cr[Mcb], g_ci[Mcb], g_zj2[Mcb];
__device__ __align__(16) float g_isp[Mcb], g_isq[Mcb], g_wfac[Mcb], g_scale[Mcb];
__device__ float g_z2[Bq];
__device__ float g_den[Bq];
__device__ float g_dpart[Bq * 256];
__device__ float g_opart[2 * Bq * 512];   // K-split partials of out GEMM

// ---------------- helpers ----------------
__device__ __forceinline__ uint32_t smem_u32(const void* p) {
    uint32_t a;
    asm("{ .reg .u64 t; cvta.to.shared.u64 t, %1; cvt.u32.u64 %0, t; }" : "=r"(a) : "l"(p));
    return a;
}
__device__ __forceinline__ void cpa16(uint32_t s, const void* g) {
    asm volatile("{ .reg .u64 gg; cvta.to.global.u64 gg, %1; cp.async.cg.shared.global [%0], [gg], 16; }"
                 :: "r"(s), "l"(g) : "memory");
}
__device__ __forceinline__ void cpa_commit() { asm volatile("cp.async.commit_group;" ::: "memory"); }
__device__ __forceinline__ void cpa_wait0() { asm volatile("cp.async.wait_group 0;" ::: "memory"); }
__device__ __forceinline__ void cpa_wait1() { asm volatile("cp.async.wait_group 1;" ::: "memory"); }

__device__ __forceinline__ void mma_bf16(float* d, const uint32_t* a, const uint32_t* b) {
    asm volatile("mma.sync.aligned.m16n8k16.row.col.f32.bf16.bf16.f32 "
                 "{%0,%1,%2,%3}, {%4,%5,%6,%7}, {%8,%9}, {%0,%1,%2,%3};"
                 : "+f"(d[0]), "+f"(d[1]), "+f"(d[2]), "+f"(d[3])
                 : "r"(a[0]), "r"(a[1]), "r"(a[2]), "r"(a[3]), "r"(b[0]), "r"(b[1]));
}
__device__ __forceinline__ void ldmx4(uint32_t* r, uint32_t a) {
    asm volatile("ldmatrix.sync.aligned.m8n8.x4.shared.b16 {%0,%1,%2,%3}, [%4];"
                 : "=r"(r[0]), "=r"(r[1]), "=r"(r[2]), "=r"(r[3]) : "r"(a));
}
__device__ __forceinline__ uint32_t swz(uint32_t o) { return o ^ ((o >> 3) & 0x70); }

__device__ __forceinline__ void wsplit(__nv_bfloat16* ph, __nv_bfloat16* pl, float x) {
    __nv_bfloat16 h = __float2bfloat16(x);
    *ph = h;
    *pl = __float2bfloat16(x - __bfloat162float(h));
}
__device__ __forceinline__ void split2w(float x, float y, uint32_t& hw, uint32_t& lw) {
    __nv_bfloat16 hx = __float2bfloat16(x), hy = __float2bfloat16(y);
    __nv_bfloat16 lx = __float2bfloat16(x - __bfloat162float(hx));
    __nv_bfloat16 ly = __float2bfloat16(y - __bfloat162float(hy));
    hw = ((uint32_t)__bfloat16_as_ushort(hy) << 16) | __bfloat16_as_ushort(hx);
    lw = ((uint32_t)__bfloat16_as_ushort(ly) << 16) | __bfloat16_as_ushort(lx);
}

// ---------------------------------------------------------------------------
// prep kernels
// ---------------------------------------------------------------------------
__global__ void prep_q(const float* __restrict__ zr, const float* __restrict__ zi,
                       const float* __restrict__ dr, const float* __restrict__ di) {
    int b = blockIdx.x, t = threadIdx.x;
    __shared__ float s1[128], s2[128];
    float drv = dr[b*Ndim+t], dvv = di[b*Ndim+t];
    float zrv = zr[b*Ndim+t], ziv = zi[b*Ndim+t];
    s1[t] = drv*drv + dvv*dvv;
    s2[t] = zrv*zrv + ziv*ziv;
    __syncthreads();
    for (int o = 64; o > 0; o >>= 1) { if (t < o) { s1[t]+=s1[t+o]; s2[t]+=s2[t+o]; } __syncthreads(); }
    float n = sqrtf(s1[0]); if (n == 0.0f) n = 1.0f;
    float inv = 1.0f / n;
    float ur = drv*inv, ui = dvv*inv;
    wsplit(&g_Ah[0][b*256+t],     &g_Al[0][b*256+t],     zrv);
    wsplit(&g_Ah[0][b*256+128+t], &g_Al[0][b*256+128+t], ziv);
    wsplit(&g_Ah[1][b*256+t],     &g_Al[1][b*256+t],     ur);
    wsplit(&g_Ah[1][b*256+128+t], &g_Al[1][b*256+128+t], ui);
    if (t == 0) g_z2[b] = s2[0];
}

__global__ void prep_c(const float* __restrict__ zjr, const float* __restrict__ zji,
                       const float* __restrict__ djr, const float* __restrict__ dji,
                       const float* __restrict__ alpha, const float* __restrict__ spv,
                       const float* __restrict__ sqv) {
    int m = blockIdx.x, t = threadIdx.x;
    __shared__ float s1[128], s2[128], s3[128];
    float ar = djr[m*Ndim+t], ai = dji[m*Ndim+t];
    s1[t] = ar*ar + ai*ai;
    __syncthreads();
    for (int o = 64; o > 0; o >>= 1) { if (t < o) s1[t]+=s1[t+o]; __syncthreads(); }
    float n = sqrtf(s1[0]); if (n == 0.0f) n = 1.0f;
    float inv = 1.0f / n;
    ar *= inv; ai *= inv;
    float br = zjr[m*Ndim+t], bi = zji[m*Ndim+t];
    wsplit(&g_Bh[0][m*256+t],     &g_Bl[0][m*256+t],     ar);
    wsplit(&g_Bh[0][m*256+128+t], &g_Bl[0][m*256+128+t], ai);
    wsplit(&g_Bh[1][m*256+t],     &g_Bl[1][m*256+t],     -ai);
    wsplit(&g_Bh[1][m*256+128+t], &g_Bl[1][m*256+128+t], ar);
    wsplit(&g_Bh[2][m*256+t],     &g_Bl[2][m*256+t],     br);
    wsplit(&g_Bh[2][m*256+128+t], &g_Bl[2][m*256+128+t], bi);
    __syncthreads();
    s1[t] = ar*br + ai*bi;
    s2[t] = ar*bi - ai*br;
    s3[t] = br*br + bi*bi;
    __syncthreads();
    for (int o = 64; o > 0; o >>= 1) {
        if (t < o) { s1[t]+=s1[t+o]; s2[t]+=s2[t+o]; s3[t]+=s3[t+o]; }
        __syncthreads();
    }
    if (t == 0) {
        float a  = fmaxf(alpha[m], TINY);
        float sp = fmaxf(spv[m], TINY);
        float sq = fmaxf(sqv[m], TINY);
        g_cr[m] = s1[0]; g_ci[m] = s2[0]; g_zj2[m] = s3[0];
        g_isp[m] = PI_F / sp;
        g_isq[m] = PI_F / sq;
        g_scale[m] = sqrtf(sp / PI_F);
        g_wfac[m] = a * sqrtf(sp) / PI_F;
    }
}

// Tcat^T[scat][m], hi/lo split.  grid (16, 256), block (32, 8)
__global__ void prep_T(const float* __restrict__ Tre, const float* __restrict__ Tim) {
    __shared__ float tile[32][33];
    int sx = blockIdx.x * 32, my = blockIdx.y * 32;
    int tx = threadIdx.x, ty = threadIdx.y;
    const float* Ts = (sx < Spay) ? Tre : Tim;
    int sl = sx & (Spay - 1);
#pragma unroll
    for (int i = 0; i < 4; i++) {
        int ml = ty + i * 8;
        tile[tx][ml] = Ts[(my + ml) * Spay + sl + tx];
    }
    __syncthreads();
#pragma unroll
    for (int i = 0; i < 4; i++) {
        int srow = sx + ty + i * 8;
        float v = tile[ty + i * 8][tx];
        wsplit(&g_Tth[(size_t)srow * Mcb + my + tx], &g_Ttl[(size_t)srow * Mcb + my + tx], v);
    }
}

// ---------------------------------------------------------------------------
// wkern: split-bf16 mma.sync 5-acc GEMM (128b x 64m) + quadrature epilogue
// 3-stage cp.async pipeline, one barrier per chunk.
// ---------------------------------------------------------------------------
#define WA_REG 32768
#define WB_REG 24576
#define WSTG   (WA_REG + WB_REG)   // 57344
#define WSMEM  (3 * WSTG)          // 172032

__global__ __launch_bounds__(256, 1) void wkern() {
    extern __shared__ __align__(16) uint8_t sm[];
    const uint32_t smb = smem_u32(sm);
    const int t = threadIdx.x, wid = t >> 5, lane = t & 31;
    const int mCTA = blockIdx.x, bCTA = blockIdx.y;
    const int wb = wid >> 1, wm = wid & 1;

    float acc[5][2][4][4] = {};

    auto issue = [&](int ch) {
        int s = ch % 3;
        int grp = ch >> 2;                 // 0: hh, 1: lo(A)*hi(B), 2: hi(A)*lo(B)
        int k0 = (ch & 3) * 64;
        uint32_t dstA = smb + s * WSTG;
        uint32_t dstB = dstA + WA_REG;
        const __nv_bfloat16* A0 = (grp == 1) ? g_Al[0] : g_Ah[0];
        const __nv_bfloat16* A1 = (grp == 1) ? g_Al[1] : g_Ah[1];
        const __nv_bfloat16* B0 = (grp == 2) ? g_Bl[0] : g_Bh[0];
        const __nv_bfloat16* B1 = (grp == 2) ? g_Bl[1] : g_Bh[1];
        const __nv_bfloat16* B2 = (grp == 2) ? g_Bl[2] : g_Bh[2];
        const __nv_bfloat16* As[2] = {A0, A1};
        const __nv_bfloat16* Bs[3] = {B0, B1, B2};
#pragma unroll
        for (int i = 0; i < 8; i++) {      // A: 2048 granules of 16B
            int g = i * 256 + t;
            int var = g >> 10, row = (g >> 3) & 127, c16 = g & 7;
            const void* src = As[var] + (size_t)(bCTA*128 + row)*256 + k0 + c16*8;
            cpa16(dstA + var*16384 + swz(row*128 + c16*16), src);
        }
#pragma unroll
        for (int i = 0; i < 6; i++) {      // B: 1536 granules
            int g = i * 256 + t;
            int var = g >> 9, row = (g >> 3) & 63, c16 = g & 7;
            const void* src = Bs[var] + (size_t)(mCTA*64 + row)*256 + k0 + c16*8;
            cpa16(dstB + var*8192 + swz(row*128 + c16*16), src);
        }
        cpa_commit();
    };

    // ldmatrix per-lane row components
    const int arow = wb*32 + ((lane >> 3) & 1)*8 + (lane & 7);   // + bt*16
    const int ac16 = lane >> 4;                                   // + kt*2
    const int brow_in = ((lane >> 4) ? 8 : 0) + (lane & 7);       // nt parity*8 + row
    const int bk16 = (lane >> 3) & 1;                             // + kt*2

    auto compute = [&](int s) {
        uint32_t baseA = smb + s * WSTG;
        uint32_t baseB = baseA + WA_REG;
#pragma unroll
        for (int kt = 0; kt < 4; kt++) {
            uint32_t af[2][2][4];
#pragma unroll
            for (int var = 0; var < 2; var++)
#pragma unroll
                for (int bt = 0; bt < 2; bt++) {
                    uint32_t o = (uint32_t)(arow + bt*16)*128 + (kt*2 + ac16)*16;
                    ldmx4(af[var][bt], baseA + var*16384 + swz(o));
                }
#pragma unroll
            for (int VAR = 0; VAR < 3; VAR++) {
#pragma unroll
                for (int np = 0; np < 2; np++) {
                    uint32_t bf[4];
                    uint32_t o = (uint32_t)((wm*4 + np*2)*8 + brow_in)*128 + (kt*2 + bk16)*16;
                    ldmx4(bf, baseB + VAR*8192 + swz(o));
#pragma unroll
                    for (int h = 0; h < 2; h++) {
                        int nt = np*2 + h;
                        const uint32_t* bsel = &bf[h*2];
                        if (VAR == 0) {
                            mma_bf16(acc[0][0][nt], af[0][0], bsel); mma_bf16(acc[0][1][nt], af[0][1], bsel);
                            mma_bf16(acc[3][0][nt], af[1][0], bsel); mma_bf16(acc[3][1][nt], af[1][1], bsel);
                        } else if (VAR == 1) {
                            mma_bf16(acc[1][0][nt], af[0][0], bsel); mma_bf16(acc[1][1][nt], af[0][1], bsel);
                            mma_bf16(acc[4][0][nt], af[1][0], bsel); mma_bf16(acc[4][1][nt], af[1][1], bsel);
                        } else {
                            mma_bf16(acc[2][0][nt], af[0][0], bsel); mma_bf16(acc[2][1][nt], af[0][1], bsel);
                        }
                    }
                }
            }
        }
    };

    issue(0);
    issue(1);
    for (int ch = 0; ch < 12; ch++) {
        if (ch < 11) cpa_wait1(); else cpa_wait0();
        __syncthreads();
        if (ch < 10) issue(ch + 2);
        compute(ch % 3);
    }

    // ---- epilogue ----
    const int mBase = mCTA*64 + wm*32 + ((lane & 3) << 1);
    float2 crv[4], civ[4], zjv[4], ipv[4], iqv[4], wfv[4], scv[4];
#pragma unroll
    for (int nt = 0; nt < 4; nt++) {
        int m = mBase + nt*8;
        crv[nt] = *(const float2*)&g_cr[m];   civ[nt] = *(const float2*)&g_ci[m];
        zjv[nt] = *(const float2*)&g_zj2[m];  ipv[nt] = *(const float2*)&g_isp[m];
        iqv[nt] = *(const float2*)&g_isq[m];  wfv[nt] = *(const float2*)&g_wfac[m];
        scv[nt] = *(const float2*)&g_scale[m];
    }
    const int rBase = bCTA*128 + wb*32 + (lane >> 2);

#pragma unroll
    for (int bt = 0; bt < 2; bt++) {
        float rs[2] = {0.0f, 0.0f};
        float wv[4][4];
        float z2v[2] = { g_z2[rBase + bt*16], g_z2[rBase + bt*16 + 8] };
#pragma unroll
        for (int nt = 0; nt < 4; nt++) {
#pragma unroll
            for (int c = 0; c < 4; c++) {
                int h = c >> 1, j = c & 1;
                float cr = j ? crv[nt].y : crv[nt].x;
                float ci = j ? civ[nt].y : civ[nt].x;
                float zj = j ? zjv[nt].y : zjv[nt].x;
                float ip = j ? ipv[nt].y : ipv[nt].x;
                float iq = j ? iqv[nt].y : iqv[nt].x;
                float wf = j ? wfv[nt].y : wfv[nt].x;
                float sc = j ? scv[nt].y : scv[nt].x;
                float a1 = acc[0][bt][nt][c], a2 = acc[1][bt][nt][c];
                float a3 = acc[2][bt][nt][c], a4 = acc[3][bt][nt][c], a5 = acc[4][bt][nt][c];
                float pr = a1 - cr;
                float pim = a2 - ci;
                float dz2 = z2v[h] + zj - 2.0f * a3;
                float perp2 = fmaxf(dz2 - (pr*pr + pim*pim), 0.0f);
                float align_ = a4*a4 + a5*a5;
                float base = -ip * (pim*pim) - iq * perp2;
                float ssum = 0.0f;
#pragma unroll
                for (int k = 0; k < 8; k++) {
                    float d = pr - GHT[k] * sc;
                    ssum += GHW[k] * __expf(fmaf(-ip * d, d, base));
                }
                float w = wf * align_ * ssum;
                wv[nt][c] = w;
                rs[h] += w;
            }
        }
#pragma unroll
        for (int h = 0; h < 2; h++) {
            float v = rs[h];
            v += __shfl_xor_sync(0xffffffffu, v, 1);
            v += __shfl_xor_sync(0xffffffffu, v, 2);
            if ((lane & 3) == 0)
                g_dpart[(rBase + bt*16 + h*8) * 256 + mCTA*2 + wm] = v;
        }
#pragma unroll
        for (int h = 0; h < 2; h++) {
            size_t rowoff = (size_t)(rBase + bt*16 + h*8) * Mcb;
#pragma unroll
            for (int nt = 0; nt < 4; nt++) {
                uint32_t hw, lw;
                split2w(wv[nt][h*2], wv[nt][h*2 + 1], hw, lw);
                *(uint32_t*)&g_Whi[rowoff + mBase + nt*8] = hw;
                *(uint32_t*)&g_Wlo[rowoff + mBase + nt*8] = lw;
            }
        }
    }
}

// ---------------------------------------------------------------------------
__global__ void denk() {
    int b = blockIdx.x, t = threadIdx.x;
    __shared__ float sh[256];
    sh[t] = g_dpart[b * 256 + t];
    __syncthreads();
    for (int o = 128; o > 0; o >>= 1) { if (t < o) sh[t] += sh[t + o]; __syncthreads(); }
    if (t == 0) g_den[b] = sh[0] + EPST;
}

// ---------------------------------------------------------------------------
// outk: partial out = W @ Tcat over a K-split. CTA 64b x 64scat.
// Fused chunk: {Whi, Wlo, Thi, Tlo} loaded once, 3 split products computed.
// grid (8 s, 16 b, 2 ksplit), 3-stage pipeline, occ 2.
// ---------------------------------------------------------------------------
#define OTILE 8192
#define OSTG  (4 * OTILE)   // 32768
#define OSMEM (3 * OSTG)    // 98304

__global__ __launch_bounds__(256, 2) void outk() {
    extern __shared__ __align__(16) uint8_t sm[];
    const uint32_t smb = smem_u32(sm);
    const int t = threadIdx.x, wid = t >> 5, lane = t & 31;
    const int sCTA = blockIdx.x, bCTA = blockIdx.y, kz = blockIdx.z;
    const int wb = wid >> 1, ws = wid & 1;
    const int b0 = bCTA * 64, s0 = sCTA * 64;
    const int kbase = kz * 4096;

    float acc[4][4] = {};

    auto issue = [&](int ch) {
        int s = ch % 3;
        int k0 = kbase + ch * 64;
        uint32_t dst = smb + s * OSTG;
        const __nv_bfloat16* srcs[4] = { g_Whi, g_Wlo, g_Tth, g_Ttl };
        const int r0[4] = { b0, b0, s0, s0 };
#pragma unroll
        for (int ti = 0; ti < 4; ti++) {
#pragma unroll
            for (int i = 0; i < 2; i++) {   // 512 granules per tile
                int g = i * 256 + t;
                int row = g >> 3, c16 = g & 7;
                cpa16(dst + ti*OTILE + swz(row*128 + c16*16),
                      srcs[ti] + (size_t)(r0[ti] + row)*Mcb + k0 + c16*8);
            }
        }
        cpa_commit();
    };

    const int arow = wb*16 + ((lane >> 3) & 1)*8 + (lane & 7);
    const int ac16 = lane >> 4;
    const int brow_in = ((lane >> 4) ? 8 : 0) + (lane & 7);
    const int bk16 = (lane >> 3) & 1;

    auto compute = [&](int s) {
        uint32_t base = smb + s * OSTG;
#pragma unroll
        for (int kt = 0; kt < 4; kt++) {
            uint32_t ah[4], al[4];
            uint32_t oA = (uint32_t)arow*128 + (kt*2 + ac16)*16;
            ldmx4(ah, base + swz(oA));
            ldmx4(al, base + OTILE + swz(oA));
#pragma unroll
            for (int np = 0; np < 2; np++) {
                uint32_t bh[4], bl[4];
                uint32_t oB = (uint32_t)((ws*4 + np*2)*8 + brow_in)*128 + (kt*2 + bk16)*16;
                ldmx4(bh, base + 2*OTILE + swz(oB));
                ldmx4(bl, base + 3*OTILE + swz(oB));
#pragma unroll
                for (int h = 0; h < 2; h++) {
                    float* a = acc[np*2 + h];
                    mma_bf16(a, ah, &bh[h*2]);
                    mma_bf16(a, al, &bh[h*2]);
                    mma_bf16(a, ah, &bl[h*2]);
                }
            }
        }
    };

    issue(0);
    issue(1);
    for (int ch = 0; ch < 64; ch++) {
        if (ch < 63) cpa_wait1(); else cpa_wait0();
        __syncthreads();
        if (ch < 62) issue(ch + 2);
        compute(ch % 3);
    }

    const int sBase = s0 + ws*32 + ((lane & 3) << 1);
    const int rB = b0 + wb*16 + (lane >> 2);
    float* part = g_opart + (size_t)kz * Bq * 512;
#pragma unroll
    for (int h = 0; h < 2; h++) {
        int b = rB + h*8;
#pragma unroll
        for (int nt = 0; nt < 4; nt++) {
            int scat = sBase + nt*8;
            *(float2*)&part[(size_t)b * 512 + scat] =
                make_float2(acc[nt][h*2], acc[nt][h*2 + 1]);
        }
    }
}

// ---------------------------------------------------------------------------
// fink: out = (part0 + part1) / den, interleave [B,S,2]
// ---------------------------------------------------------------------------
__global__ void fink(float* __restrict__ out) {
    int b = blockIdx.x, t = threadIdx.x;
    float inv = 1.0f / g_den[b];
#pragma unroll
    for (int i = 0; i < 2; i++) {
        int scat = i * 256 + t;
        float v = (g_opart[(size_t)b * 512 + scat] +
                   g_opart[(size_t)(Bq + b) * 512 + scat]) * inv;
        int c = scat >> 8;
        int sl = scat & (Spay - 1);
        out[((size_t)b * Spay + sl) * 2 + c] = v;
    }
}

// ---------------------------------------------------------------------------
extern "C" void kernel_launch(void* const* d_in, const int* in_sizes, int n_in,
                              void* d_out, int out_size) {
    const float* z_re  = (const float*)d_in[0];
    const float* z_im  = (const float*)d_in[1];
    const float* d_re  = (const float*)d_in[2];
    const float* d_im  = (const float*)d_in[3];
    const float* zj_re = (const float*)d_in[4];
    const float* zj_im = (const float*)d_in[5];
    const float* dj_re = (const float*)d_in[6];
    const float* dj_im = (const float*)d_in[7];
    const float* T_re  = (const float*)d_in[8];
    const float* T_im  = (const float*)d_in[9];
    const float* alpha = (const float*)d_in[10];
    const float* s_par = (const float*)d_in[11];
    const float* s_perp = (const float*)d_in[12];
    float* out = (float*)d_out;

    cudaFuncSetAttribute(wkern, cudaFuncAttributeMaxDynamicSharedMemorySize, WSMEM);
    cudaFuncSetAttribute(outk,  cudaFuncAttributeMaxDynamicSharedMemorySize, OSMEM);

    prep_q<<<Bq, 128>>>(z_re, z_im, d_re, d_im);
    prep_c<<<Mcb, 128>>>(zj_re, zj_im, dj_re, dj_im, alpha, s_par, s_perp);
    prep_T<<<dim3(512 / 32, Mcb / 32), dim3(32, 8)>>>(T_re, T_im);
    wkern<<<dim3(Mcb / 64, Bq / 128), 256, WSMEM>>>();
    denk<<<Bq, 256>>>();
    outk<<<dim3(8, 16, 2), 256, OSMEM>>>();
    fink<<<Bq, 256>>>(out);
}